// round 12
// baseline (speedup 1.0000x reference)
#include <cuda_runtime.h>
#include <cuda_bf16.h>

// SoftPerspectiveShader: fused sample_textures + softmax_rgb_blend
// R11 = EXACT R1 body (best kernel: 42.5us, DRAM 66%) with two chip-level
// changes, zero intra-warp changes:
//  1. Persistent grid-stride loop: 760 blocks (5/SM x 152 SMs) instead of
//     4096 blocks in 5.5 waves -> removes ~4.5 wave transitions (~2360cyc
//     each) and re-paid per-wave L1tex-queue spread.
//  2. L2 policy: __ldcs (evict-first) on the 4 streaming tensors and
//     __stcs on the output, so the 160MB stream stops competing with the
//     7.2MB L2-resident face_colors gather table.
// Arithmetic is bit-identical to R1 (accurate expf, true divides).
// Softmax is effectively one-hot (GAMMA=1e-4, zbuf sorted): w==0
// fragments contribute exactly 0, so their bary/fcol gathers are skipped.

#define SIGMA_F 1e-4f
#define GAMMA_F 1e-4f
#define ZNEAR_F 1.0f
#define ZFAR_F  100.0f
#define EPS_F   1e-10f

#define THREADS 256
#define NBLOCKS 760   // 5 blocks/SM x 152 SMs: one persistent wave

__global__ __launch_bounds__(THREADS, 5) void soft_shader_kernel(
    const int4*   __restrict__ p2f,    // [P][2] int4  (K=8)
    const float*  __restrict__ bary,   // [P][8][3]
    const float4* __restrict__ zbuf,   // [P][2] float4
    const float4* __restrict__ dists,  // [P][2] float4
    const float*  __restrict__ fcol,   // [F][3][3]
    float4*       __restrict__ out,    // [P]
    int P)
{
    const int stride = gridDim.x * blockDim.x;

#pragma unroll 1
    for (int p = blockIdx.x * blockDim.x + threadIdx.x; p < P; p += stride) {
        // ---- front batch: 6 independent streaming LDG.128 (evict-first) ----
        const int4   fa = __ldcs(&p2f[2 * p]),   fb = __ldcs(&p2f[2 * p + 1]);
        const float4 za = __ldcs(&zbuf[2 * p]),  zb = __ldcs(&zbuf[2 * p + 1]);
        const float4 da = __ldcs(&dists[2 * p]), db = __ldcs(&dists[2 * p + 1]);

        int   faces[8] = {fa.x, fa.y, fa.z, fa.w, fb.x, fb.y, fb.z, fb.w};
        float zv[8]    = {za.x, za.y, za.z, za.w, zb.x, zb.y, zb.z, zb.w};
        float dv[8]    = {da.x, da.y, da.z, da.w, db.x, db.y, db.z, db.w};

        float prob[8], zinv[8];
        float zmax = EPS_F;      // z_inv_max = max(max_k z_inv, EPS)
        float keep = 1.0f;       // prod(1 - prob) = 1 - alpha

#pragma unroll
        for (int k = 0; k < 8; k++) {
            bool  m  = faces[k] >= 0;
            // sigmoid(-d/sigma) = 1/(1+exp(d/sigma))
            float pr = m ? (1.0f / (1.0f + expf(dv[k] / SIGMA_F))) : 0.0f;
            prob[k] = pr;
            keep *= (1.0f - pr);
            float zi = m ? ((ZFAR_F - zv[k]) / (ZFAR_F - ZNEAR_F)) : 0.0f;
            zinv[k] = zi;
            zmax = fmaxf(zmax, zi);
        }

        float delta = fmaxf(expf((EPS_F - zmax) / GAMMA_F), EPS_F);
        float denom = delta;
        float r = 0.0f, g = 0.0f, b = 0.0f;

#pragma unroll
        for (int k = 0; k < 8; k++) {
            float w = prob[k] * expf((zinv[k] - zmax) / GAMMA_F);
            denom += w;
            if (w > 0.0f) {
                // w > 0 implies faces[k] >= 0
                const float* bc = bary + (size_t)p * 24 + (size_t)k * 3;
                float b0 = __ldcs(bc + 0), b1 = __ldcs(bc + 1), b2 = __ldcs(bc + 2);
                const float* fc = fcol + (size_t)faces[k] * 9;   // L2-resident table
                float t0 = b0 * fc[0] + b1 * fc[3] + b2 * fc[6];
                float t1 = b0 * fc[1] + b1 * fc[4] + b2 * fc[7];
                float t2 = b0 * fc[2] + b1 * fc[5] + b2 * fc[8];
                r += w * t0;
                g += w * t1;
                b += w * t2;
            }
        }

        float inv = 1.0f / denom;
        float4 o;
        o.x = (r + delta) * inv;   // background = (1,1,1): + delta*1/denom
        o.y = (g + delta) * inv;
        o.z = (b + delta) * inv;
        o.w = keep;                // 1 - alpha
        __stcs(&out[p], o);
    }
}

extern "C" void kernel_launch(void* const* d_in, const int* in_sizes, int n_in,
                              void* d_out, int out_size) {
    const int*   p2f   = (const int*)d_in[0];
    const float* bary  = (const float*)d_in[1];
    const float* zbufp = (const float*)d_in[2];
    const float* dist  = (const float*)d_in[3];
    const float* fcol  = (const float*)d_in[4];
    int P = in_sizes[0] / 8;   // N*H*W pixels

    soft_shader_kernel<<<NBLOCKS, THREADS>>>(
        (const int4*)p2f, bary, (const float4*)zbufp, (const float4*)dist,
        fcol, (float4*)d_out, P);
}

// round 13
// speedup vs baseline: 1.4294x; 1.4294x over previous
#include <cuda_runtime.h>
#include <cuda_bf16.h>

// SoftPerspectiveShader: fused sample_textures + softmax_rgb_blend
// R12 = EXACT R1 (best: 43.5us bench / 42.5us ncu, DRAM 66%) with exactly
// ONE change: evict-first cache policy (__ldcs/__stcs) on the six bulk
// 16B streaming loads and the 16B output store. These are touched exactly
// once; default policy let them evict the 7.2MB face_colors gather table
// from L2, which explains the ~70MB of measured DRAM traffic above the
// analytic floor (224MB vs ~151MB). bary + fcol keep DEFAULT policy
// (R11 showed .cs on the scalar bary loads wrecks L1 coalescing).
// Arithmetic bit-identical to R1. Softmax is effectively one-hot
// (GAMMA=1e-4, zbuf sorted): w==0 fragments contribute exactly 0, so
// their bary/fcol gathers are skipped.

#define SIGMA_F 1e-4f
#define GAMMA_F 1e-4f
#define ZNEAR_F 1.0f
#define ZFAR_F  100.0f
#define EPS_F   1e-10f

__global__ __launch_bounds__(256) void soft_shader_kernel(
    const int4*   __restrict__ p2f,    // [P][2] int4  (K=8)
    const float*  __restrict__ bary,   // [P][8][3]
    const float4* __restrict__ zbuf,   // [P][2] float4
    const float4* __restrict__ dists,  // [P][2] float4
    const float*  __restrict__ fcol,   // [F][3][3]
    float4*       __restrict__ out,    // [P]
    int P)
{
    int p = blockIdx.x * blockDim.x + threadIdx.x;
    if (p >= P) return;

    // ---- front batch: 6 independent LDG.E.128.CS (evict-first, stream) ----
    const int4   fa = __ldcs(&p2f[2 * p]),   fb = __ldcs(&p2f[2 * p + 1]);
    const float4 za = __ldcs(&zbuf[2 * p]),  zb = __ldcs(&zbuf[2 * p + 1]);
    const float4 da = __ldcs(&dists[2 * p]), db = __ldcs(&dists[2 * p + 1]);

    int   faces[8] = {fa.x, fa.y, fa.z, fa.w, fb.x, fb.y, fb.z, fb.w};
    float zv[8]    = {za.x, za.y, za.z, za.w, zb.x, zb.y, zb.z, zb.w};
    float dv[8]    = {da.x, da.y, da.z, da.w, db.x, db.y, db.z, db.w};

    float prob[8], zinv[8];
    float zmax = EPS_F;      // z_inv_max = max(max_k z_inv, EPS)
    float keep = 1.0f;       // prod(1 - prob) = 1 - alpha

#pragma unroll
    for (int k = 0; k < 8; k++) {
        bool  m  = faces[k] >= 0;
        // sigmoid(-d/sigma) = 1/(1+exp(d/sigma)); matches jax stable sigmoid
        float pr = m ? (1.0f / (1.0f + expf(dv[k] / SIGMA_F))) : 0.0f;
        prob[k] = pr;
        keep *= (1.0f - pr);
        float zi = m ? ((ZFAR_F - zv[k]) / (ZFAR_F - ZNEAR_F)) : 0.0f;
        zinv[k] = zi;
        zmax = fmaxf(zmax, zi);
    }

    float delta = fmaxf(expf((EPS_F - zmax) / GAMMA_F), EPS_F);
    float denom = delta;
    float r = 0.0f, g = 0.0f, b = 0.0f;

#pragma unroll
    for (int k = 0; k < 8; k++) {
        float w = prob[k] * expf((zinv[k] - zmax) / GAMMA_F);
        denom += w;
        if (w > 0.0f) {
            // w > 0 implies prob > 0 implies faces[k] >= 0
            // DEFAULT cache policy here: bary sector may be re-touched by
            // neighbors; fcol table must stay L2-resident.
            const float* bc = bary + (size_t)p * 24 + (size_t)k * 3;
            float b0 = bc[0], b1 = bc[1], b2 = bc[2];
            const float* fc = fcol + (size_t)faces[k] * 9;
            float t0 = b0 * fc[0] + b1 * fc[3] + b2 * fc[6];
            float t1 = b0 * fc[1] + b1 * fc[4] + b2 * fc[7];
            float t2 = b0 * fc[2] + b1 * fc[5] + b2 * fc[8];
            r += w * t0;
            g += w * t1;
            b += w * t2;
        }
    }

    float inv = 1.0f / denom;
    float4 o;
    o.x = (r + delta) * inv;   // background = (1,1,1): + delta*1/denom
    o.y = (g + delta) * inv;
    o.z = (b + delta) * inv;
    o.w = keep;                // 1 - alpha
    __stcs(&out[p], o);        // write-once output, evict-first
}

extern "C" void kernel_launch(void* const* d_in, const int* in_sizes, int n_in,
                              void* d_out, int out_size) {
    const int*   p2f   = (const int*)d_in[0];
    const float* bary  = (const float*)d_in[1];
    const float* zbufp = (const float*)d_in[2];
    const float* dist  = (const float*)d_in[3];
    const float* fcol  = (const float*)d_in[4];
    int P = in_sizes[0] / 8;   // N*H*W pixels

    int threads = 256;
    int blocks  = (P + threads - 1) / threads;
    soft_shader_kernel<<<blocks, threads>>>(
        (const int4*)p2f, bary, (const float4*)zbufp, (const float4*)dist,
        fcol, (float4*)d_out, P);
}